// round 2
// baseline (speedup 1.0000x reference)
#include <cuda_runtime.h>
#include <math_constants.h>

#define BATCH 32
#define CDIM 256
#define HW 4096
#define NCODES 1024
#define NPIX (BATCH * HW)

#define PIX_TILE 128
#define CK 16

// ---------------- scratch ----------------
__device__ float g_enorm[NCODES];

// ---------------- ||e_k||^2 : strict sequential, round-per-op (no FMA) ----------------
__global__ void enorm_kernel(const float* __restrict__ cb) {
    int k = blockIdx.x * blockDim.x + threadIdx.x;   // 1024 threads total
    if (k >= NCODES) return;
    float acc = 0.f;
    const float* row = cb + k * CDIM;
    for (int c = 0; c < CDIM; ++c) {
        float v = row[c];
        acc = __fadd_rn(acc, __fmul_rn(v, v));       // fl(v*v) then fl(add): matches eager mul->sum
    }
    g_enorm[k] = acc;
}

// ---------------- main VQ kernel ----------------
// smem layout (floats):
//   [0, 33792)            Zs[c][p] (256x128, uses 32768) ; reused as gbuf[c][p] pitch 132 (uses 33792)
//   [33792, 37888)        bs: double-buffered codebook chunk 2 x (16 x 128)
//   [37888, 39936)        rval: 128 pixels x 16 partial mins
//   [39936, 41984)        ridx: 128 x 16 (int)
//   [41984, 42112)        idxf: 128 final indices (int)
//   [42112, 42240)        zns: 128 ||z||^2 values
#define SM_ZS    0
#define SM_BS    33792
#define SM_RVAL  (33792 + 4096)
#define SM_RIDX  (33792 + 4096 + 2048)
#define SM_IDXF  (33792 + 4096 + 4096)
#define SM_ZNS   (33792 + 4096 + 4096 + 128)
#define SM_TOTAL_FLOATS (SM_ZNS + 128)

extern __shared__ float smem[];

__global__ __launch_bounds__(256, 1)
void vq_kernel(const float* __restrict__ z, const float* __restrict__ cb,
               float* __restrict__ out) {
    float* Zs   = smem + SM_ZS;
    float* bs   = smem + SM_BS;
    float* rval = smem + SM_RVAL;
    int*   ridx = (int*)(smem + SM_RIDX);
    int*   idxf = (int*)(smem + SM_IDXF);
    float* zns  = smem + SM_ZNS;

    const int tid = threadIdx.x;
    const int tx = tid & 15;       // code sub-block
    const int ty = tid >> 4;       // pixel sub-block

    const int pb = blockIdx.x;     // 1024 blocks, 128 pixels each
    const int b  = pb >> 5;        // 32 tiles per image (4096/128)
    const int o0 = (pb & 31) * PIX_TILE;
    const int o4 = o0 >> 2;

    const float4* zg4  = (const float4*)z + (size_t)b * (CDIM * HW / 4);
    float4*       out4 = (float4*)out      + (size_t)b * (CDIM * HW / 4);
    const float4* cb4  = (const float4*)cb;

    // ---- stage z tile: Zs[c][p], fully coalesced ----
    for (int j = tid; j < CDIM * (PIX_TILE / 4); j += 256) {
        int c = j >> 5, v = j & 31;
        *(float4*)&Zs[c * PIX_TILE + v * 4] = zg4[c * (HW / 4) + o4 + v];
    }
    __syncthreads();

    // ---- ||z||^2 per pixel: strict sequential ascending-c, round-per-op ----
    if (tid < PIX_TILE) {
        float acc = 0.f;
        for (int c = 0; c < CDIM; ++c) {
            float v = Zs[c * PIX_TILE + tid];
            acc = __fadd_rn(acc, __fmul_rn(v, v));
        }
        zns[tid] = acc;
    }
    __syncthreads();

    float minv[8];
    int   mini[8];
    #pragma unroll
    for (int p = 0; p < 8; ++p) { minv[p] = CUDART_INF_F; mini[p] = 0x7fffffff; }

    const int kk = tid >> 1;       // 0..127 code row within tile
    const int part = tid & 1;      // which 8-float half of the 16-c chunk

    float znp[8];
    #pragma unroll
    for (int p = 0; p < 8; ++p) znp[p] = zns[ty * 8 + p];

    for (int kt = 0; kt < 8; ++kt) {
        const int k0 = kt * 128;
        float acc[8][8];
        #pragma unroll
        for (int p = 0; p < 8; ++p)
            #pragma unroll
            for (int q = 0; q < 8; ++q) acc[p][q] = 0.f;

        // prefetch chunk 0 of this code tile
        float4 r0, r1;
        {
            const float* src = &cb[(k0 + kk) * CDIM + part * 8];
            r0 = *(const float4*)src;
            r1 = *(const float4*)(src + 4);
        }

        for (int cc = 0; cc < CDIM / CK; ++cc) {
            float* buf = &bs[(cc & 1) * (CK * 128)];
            {   // transpose-store chunk into smem: bs[s][kk]
                int sb = part * 8;
                buf[(sb + 0) * 128 + kk] = r0.x;
                buf[(sb + 1) * 128 + kk] = r0.y;
                buf[(sb + 2) * 128 + kk] = r0.z;
                buf[(sb + 3) * 128 + kk] = r0.w;
                buf[(sb + 4) * 128 + kk] = r1.x;
                buf[(sb + 5) * 128 + kk] = r1.y;
                buf[(sb + 6) * 128 + kk] = r1.z;
                buf[(sb + 7) * 128 + kk] = r1.w;
            }
            __syncthreads();
            if (cc < CDIM / CK - 1) {   // prefetch next chunk (overlaps compute)
                const float* src = &cb[(k0 + kk) * CDIM + (cc + 1) * CK + part * 8];
                r0 = *(const float4*)src;
                r1 = *(const float4*)(src + 4);
            }
            // strictly ascending c, single fused-FMA accumulator per output
            // (matches Eigen gebp depth loop semantics)
            #pragma unroll
            for (int s = 0; s < CK; ++s) {
                const float* zr = &Zs[((cc << 4) + s) * PIX_TILE + (ty << 3)];
                float4 a0 = *(const float4*)zr;
                float4 a1 = *(const float4*)(zr + 4);
                const float* br = &buf[s * 128 + (tx << 3)];
                float4 b0 = *(const float4*)br;
                float4 b1 = *(const float4*)(br + 4);
                float av[8] = {a0.x, a0.y, a0.z, a0.w, a1.x, a1.y, a1.z, a1.w};
                float bv[8] = {b0.x, b0.y, b0.z, b0.w, b1.x, b1.y, b1.z, b1.w};
                #pragma unroll
                for (int p = 0; p < 8; ++p)
                    #pragma unroll
                    for (int q = 0; q < 8; ++q)
                        acc[p][q] = __fmaf_rn(av[p], bv[q], acc[p][q]);
            }
            __syncthreads();
        }

        // ---- running min update for this code tile ----
        // d = fl( fl(zn + en) - fl(2*dot) )  — replicates eager (zn+en) - 2*mm
        float en[8];
        #pragma unroll
        for (int q = 0; q < 8; ++q) en[q] = g_enorm[k0 + tx * 8 + q];
        #pragma unroll
        for (int p = 0; p < 8; ++p) {
            #pragma unroll
            for (int q = 0; q < 8; ++q) {
                float sc = __fsub_rn(__fadd_rn(znp[p], en[q]),
                                     __fmul_rn(2.0f, acc[p][q]));
                // ascending k scan: strict < keeps the earliest (lowest) index
                if (sc < minv[p]) { minv[p] = sc; mini[p] = k0 + tx * 8 + q; }
            }
        }
    }

    // ---- cross-thread (tx) reduction: lexicographic (value, lowest index) ----
    #pragma unroll
    for (int p = 0; p < 8; ++p) {
        rval[(ty * 8 + p) * 16 + tx] = minv[p];
        ridx[(ty * 8 + p) * 16 + tx] = mini[p];
    }
    __syncthreads();
    if (tid < PIX_TILE) {
        float bv = rval[tid * 16];
        int   bi = ridx[tid * 16];
        #pragma unroll
        for (int i = 1; i < 16; ++i) {
            float v = rval[tid * 16 + i];
            int   x = ridx[tid * 16 + i];
            if (v < bv || (v == bv && x < bi)) { bv = v; bi = x; }
        }
        idxf[tid] = bi;
    }
    __syncthreads();

    // ---- gather codebook rows into gbuf[c][p] (pitch 132, reuses Zs space) ----
    float* gbuf = smem + SM_ZS;
    for (int j = tid; j < PIX_TILE * (CDIM / 4); j += 256) {
        int p = j >> 6, v = j & 63;               // v = float4 index along codebook row
        float4 e = cb4[idxf[p] * (CDIM / 4) + v]; // coalesced row read (L2-hot)
        int c = v * 4;
        gbuf[(c + 0) * 132 + p] = e.x;
        gbuf[(c + 1) * 132 + p] = e.y;
        gbuf[(c + 2) * 132 + p] = e.z;
        gbuf[(c + 3) * 132 + p] = e.w;
    }
    __syncthreads();

    // ---- write NCHW output, reproducing straight-through fp32 rounding ----
    // out = fl( z + fl(z_q - z) ), per-op rounded exactly like the eager reference
    for (int i = tid; i < CDIM * (PIX_TILE / 4); i += 256) {
        int c = i >> 5, v = i & 31;
        float4 q  = *(const float4*)&gbuf[c * 132 + v * 4];
        float4 zv = zg4[c * (HW / 4) + o4 + v];
        float4 o;
        o.x = __fadd_rn(zv.x, __fsub_rn(q.x, zv.x));
        o.y = __fadd_rn(zv.y, __fsub_rn(q.y, zv.y));
        o.z = __fadd_rn(zv.z, __fsub_rn(q.z, zv.z));
        o.w = __fadd_rn(zv.w, __fsub_rn(q.w, zv.w));
        out4[c * (HW / 4) + o4 + v] = o;
    }
}

// ---------------- launch ----------------
extern "C" void kernel_launch(void* const* d_in, const int* in_sizes, int n_in,
                              void* d_out, int out_size) {
    const float* z  = (const float*)d_in[0];   // [32, 256, 64, 64]
    const float* cb = (const float*)d_in[1];   // [1024, 256]
    float* out = (float*)d_out;

    cudaFuncSetAttribute(vq_kernel, cudaFuncAttributeMaxDynamicSharedMemorySize,
                         SM_TOTAL_FLOATS * 4);

    enorm_kernel<<<NCODES / 256, 256>>>(cb);
    vq_kernel<<<NPIX / PIX_TILE, 256, SM_TOTAL_FLOATS * 4>>>(z, cb, out);
}